// round 17
// baseline (speedup 1.0000x reference)
#include <cuda_runtime.h>
#include <cuda_bf16.h>
#include <cstdint>

// Problem constants
#define B_    8
#define L_    2048
#define D_    64
#define TOPK_ 32

// Tiling
#define TQ     32
#define CK     128
#define NCHUNK (L_ / CK)         // 16
#define NBLK   (B_ * L_ / TQ)    // 512
#define BPB    (L_ / TQ)         // 64

// Selection thresholds
#define Z_TAU  1.70f             // harvest: E[count]=91, sd=9.3
#define Z_TAU2 2.01f             // trim:    E[count2]=45, sd=6.6
#define MINC   40                // harvest containment guard
#define CAP    128               // harvest overflow guard (P~3e-5 -> fallback)
#define CAPG   160               // global candidate stride
#define TRIM   40                // fallback rank-trim size
#define TRIM2  64                // skey capacity / count2 upper guard
#define MINC2  36                // count2 lower guard

#define KST  72                  // K row stride (bf16 elems) = 144B pitch
#define CHUNK_BYTES (CK * KST * 2)   // 18432 bytes per chunk tile

// ---- dynamic smem layout (bytes) ----
#define OFF_KBF   0              // bf16 [2][128][72] = 36864  (overlaid post-loop)
#define OFF_QS    36864          // f32  [32][68]     =  8704
#define OFF_TAU   45568          // f32  [32]  (tau*8 = Z*||q||)
#define OFF_CNT   45696          // int  [32]
#define OFF_MBAR  45824          // u64  [2] (+pad)
#define OFF_TAU2  45952          // u32  [32] (packed tau2 threshold)
#define SMEM_A    46080          // x4 blocks/SM = 184320 <= 228KB

// selection overlays on the KBF region (valid only after mainloop)
#define OFF_PK    0              // u32 [32][128] = 16384 (also selv/seli per row)
#define OFF_IDS   16384          // u16 [32][64]  =  4096
#define OFF_SKEY  20480          // u64 [32][64]  = 16384   (ends 36864)

// Global scratch. gKbf is CHUNK-PADDED + per-row PERMUTED (see R15/R16).
__device__ __nv_bfloat16 gKbf[(size_t)B_ * NCHUNK * CK * KST];   // 2.25 MB
__device__ unsigned g_cand[(size_t)B_ * L_ * CAPG];              // packed (s16<<16)|idx

__device__ __forceinline__ unsigned f2sortable(float f) {
    unsigned bb = __float_as_uint(f);
    return (bb & 0x80000000u) ? ~bb : (bb | 0x80000000u);
}
__device__ __forceinline__ float s2f(unsigned u) {
    unsigned bb = (u & 0x80000000u) ? (u & 0x7FFFFFFFu) : ~u;
    return __uint_as_float(bb);
}
__device__ __forceinline__ unsigned short f2s16(float f) {
    unsigned short b = __bfloat16_as_ushort(__float2bfloat16(f));
    return (b & 0x8000) ? (unsigned short)~b : (unsigned short)(b | 0x8000);
}
__device__ __forceinline__ uint32_t pack_bf2(float lo, float hi) {
    __nv_bfloat162 h2 = __floats2bfloat162_rn(lo, hi);
    return *reinterpret_cast<uint32_t*>(&h2);
}

__device__ __forceinline__ void mma_bf16(
    float& c0, float& c1, float& c2, float& c3,
    uint32_t a0, uint32_t a1, uint32_t a2, uint32_t a3,
    uint32_t b0, uint32_t b1)
{
    asm volatile(
        "mma.sync.aligned.m16n8k16.row.col.f32.bf16.bf16.f32 "
        "{%0,%1,%2,%3}, {%4,%5,%6,%7}, {%8,%9}, {%0,%1,%2,%3};\n"
        : "+f"(c0), "+f"(c1), "+f"(c2), "+f"(c3)
        : "r"(a0), "r"(a1), "r"(a2), "r"(a3), "r"(b0), "r"(b1));
}

// ---- bulk-copy + mbarrier helpers ----
__device__ __forceinline__ void mbar_init(uint32_t mbar, uint32_t count) {
    asm volatile("mbarrier.init.shared.b64 [%0], %1;" :: "r"(mbar), "r"(count) : "memory");
}
__device__ __forceinline__ void mbar_expect_tx(uint32_t mbar, uint32_t bytes) {
    asm volatile("mbarrier.arrive.expect_tx.shared.b64 _, [%0], %1;"
                 :: "r"(mbar), "r"(bytes) : "memory");
}
__device__ __forceinline__ void bulk_g2s(uint32_t smem_dst, const void* gsrc,
                                         uint32_t bytes, uint32_t mbar) {
    asm volatile(
        "cp.async.bulk.shared::cta.global.mbarrier::complete_tx::bytes "
        "[%0], [%1], %2, [%3];"
        :: "r"(smem_dst), "l"(gsrc), "r"(bytes), "r"(mbar) : "memory");
}
__device__ __forceinline__ void mbar_wait(uint32_t mbar, uint32_t parity) {
    asm volatile(
        "{\n\t"
        ".reg .pred P;\n\t"
        "WAIT_%=: \n\t"
        "mbarrier.try_wait.parity.acquire.cta.shared::cta.b64 P, [%0], %1, 0x989680;\n\t"
        "@!P bra WAIT_%=;\n\t"
        "}"
        :: "r"(mbar), "r"(parity) : "memory");
}

// ---------------------------------------------------------------------------
// Kernel 0: K fp32 -> bf16, chunk-padded + permuted
// ---------------------------------------------------------------------------
__global__ __launch_bounds__(256) void convert_k(const float* __restrict__ k) {
    int idx = blockIdx.x * 256 + threadIdx.x;
    int r   = idx >> 3;
    int seg = idx & 7;
    const float* kr = k + (size_t)r * D_;
    int acg = seg >> 1;
    int ks0 = (seg & 1) * 2;
    int ac  = acg * 2;

    uint4 o;
    {
        int base = ks0 * 16 + ac;
        o.x = pack_bf2(kr[base],     kr[base + 1]);
        o.y = pack_bf2(kr[base + 8], kr[base + 9]);
    }
    {
        int base = (ks0 + 1) * 16 + ac;
        o.z = pack_bf2(kr[base],     kr[base + 1]);
        o.w = pack_bf2(kr[base + 8], kr[base + 9]);
    }
    int b     = r >> 11;
    int kk    = r & 2047;
    int ck    = kk >> 7;
    int keyIn = kk & 127;
    size_t rowBaseE = ((size_t)(b * NCHUNK + ck) * CK + keyIn) * KST;
    *(uint4*)((unsigned short*)gKbf + rowBaseE + seg * 8) = o;
}

// ---------------------------------------------------------------------------
// Fused: HMMA score + threshold harvest + tau2-trim + rescore + top-32
// ---------------------------------------------------------------------------
__global__ __launch_bounds__(256, 4) void fused_attn(
    const float* __restrict__ q, const float* __restrict__ k,
    const float* __restrict__ v, float* __restrict__ out)
{
    extern __shared__ __align__(16) char smem[];
    unsigned short* Kbf = (unsigned short*)(smem + OFF_KBF);
    float*    Qs    = (float*)(smem + OFF_QS);
    float*    tauA  = (float*)(smem + OFF_TAU);    // tau*8 = Z*||q||
    int*      cnt   = (int*)(smem + OFF_CNT);
    unsigned* tau2A = (unsigned*)(smem + OFF_TAU2); // packed u32 threshold

    const int t    = threadIdx.x;
    const int lane = t & 31;
    const int w    = t >> 5;
    const unsigned full = 0xffffffffu;
    const unsigned ltmask = (1u << lane) - 1u;

    const int rowBase = blockIdx.x * TQ;
    const int b       = blockIdx.x / BPB;
    const float* kb   = k + (size_t)b * L_ * D_;
    const float* vb   = v + (size_t)b * L_ * D_;
    const __nv_bfloat16* gkb = gKbf + (size_t)b * NCHUNK * CK * KST;
    const uint32_t ksBase = (uint32_t)__cvta_generic_to_shared(Kbf);
    const uint32_t mbar0  = (uint32_t)__cvta_generic_to_shared(smem + OFF_MBAR);

    for (int i = t; i < TQ * 16; i += 256) {
        int row = i >> 4, dg4 = (i & 15) << 2;
        *(float4*)(Qs + row * 68 + dg4) =
            *(const float4*)(q + ((size_t)(rowBase + row)) * D_ + dg4);
    }
    if (t < TQ) cnt[t] = 0;
    if (t == 0) { mbar_init(mbar0, 1); mbar_init(mbar0 + 8, 1); }
    __syncthreads();

    // per-row tau*8 and packed tau2
    for (int rr = 0; rr < 4; ++rr) {
        int row = w * 4 + rr;
        float x = Qs[row * 68 + lane], y = Qs[row * 68 + lane + 32];
        float nrm = x * x + y * y;
        #pragma unroll
        for (int o = 16; o >= 1; o >>= 1) nrm += __shfl_xor_sync(full, nrm, o);
        if (lane == 0) {
            float qn = sqrtf(nrm);
            tauA[row]  = Z_TAU * qn;
            tau2A[row] = (unsigned)f2s16(Z_TAU2 * qn * 0.125f) << 16;
        }
    }

    // A fragments (Q) once
    const int rg = w >> 2;
    const int ns = w & 3;
    const int qr = lane >> 2;
    const int acg = lane & 3;
    const int ar = rg * 16 + qr;
    const int ac = acg * 2;
    uint32_t afr[4][4];
    #pragma unroll
    for (int ks = 0; ks < 4; ++ks) {
        int col = ks * 16 + ac;
        afr[ks][0] = pack_bf2(Qs[ar * 68 + col],           Qs[ar * 68 + col + 1]);
        afr[ks][1] = pack_bf2(Qs[(ar + 8) * 68 + col],     Qs[(ar + 8) * 68 + col + 1]);
        afr[ks][2] = pack_bf2(Qs[ar * 68 + col + 8],       Qs[ar * 68 + col + 9]);
        afr[ks][3] = pack_bf2(Qs[(ar + 8) * 68 + col + 8], Qs[(ar + 8) * 68 + col + 9]);
    }

    // prologue: bulk-copy chunk 0
    if (t == 0) {
        mbar_expect_tx(mbar0, CHUNK_BYTES);
        bulk_g2s(ksBase, gkb, CHUNK_BYTES, mbar0);
    }

    unsigned* candRowA = g_cand + (size_t)(rowBase + ar) * CAPG;
    unsigned* candRowB = g_cand + (size_t)(rowBase + ar + 8) * CAPG;
    __syncthreads();

    const float tau_a = tauA[ar], tau_b = tauA[ar + 8];

    for (int chunk = 0; chunk < NCHUNK; ++chunk) {
        if (chunk + 1 < NCHUNK && t == 0) {
            const int nb = (chunk + 1) & 1;
            mbar_expect_tx(mbar0 + nb * 8, CHUNK_BYTES);
            bulk_g2s(ksBase + nb * CHUNK_BYTES,
                     gkb + (size_t)(chunk + 1) * CK * KST,
                     CHUNK_BYTES, mbar0 + nb * 8);
        }
        mbar_wait(mbar0 + (chunk & 1) * 8, (chunk >> 1) & 1);

        const unsigned short* Kb = Kbf + (chunk & 1) * (CK * KST);
        #pragma unroll
        for (int nt = 0; nt < 4; ++nt) {
            const int keyInChunk = ns * 32 + nt * 8 + qr;
            const uint4* bp = (const uint4*)&Kb[keyInChunk * KST + acg * 16];
            uint4 bA = bp[0];
            uint4 bB = bp[1];
            float c0 = 0.f, c1 = 0.f, c2 = 0.f, c3 = 0.f;
            mma_bf16(c0, c1, c2, c3, afr[0][0], afr[0][1], afr[0][2], afr[0][3], bA.x, bA.y);
            mma_bf16(c0, c1, c2, c3, afr[1][0], afr[1][1], afr[1][2], afr[1][3], bA.z, bA.w);
            mma_bf16(c0, c1, c2, c3, afr[2][0], afr[2][1], afr[2][2], afr[2][3], bB.x, bB.y);
            mma_bf16(c0, c1, c2, c3, afr[3][0], afr[3][1], afr[3][2], afr[3][3], bB.z, bB.w);
            const unsigned kcol = chunk * CK + ns * 32 + nt * 8 + ac;
            if (c0 >= tau_a) { float s = c0 * 0.125f; int p = atomicAdd(&cnt[ar], 1);     if (p < CAP) candRowA[p] = ((unsigned)f2s16(s) << 16) | kcol; }
            if (c1 >= tau_a) { float s = c1 * 0.125f; int p = atomicAdd(&cnt[ar], 1);     if (p < CAP) candRowA[p] = ((unsigned)f2s16(s) << 16) | (kcol + 1); }
            if (c2 >= tau_b) { float s = c2 * 0.125f; int p = atomicAdd(&cnt[ar + 8], 1); if (p < CAP) candRowB[p] = ((unsigned)f2s16(s) << 16) | kcol; }
            if (c3 >= tau_b) { float s = c3 * 0.125f; int p = atomicAdd(&cnt[ar + 8], 1); if (p < CAP) candRowB[p] = ((unsigned)f2s16(s) << 16) | (kcol + 1); }
        }
        __syncthreads();
    }
    // mainloop done; overlay selection arrays on KBF region

    unsigned* pkA = (unsigned*)(smem + OFF_PK);
    unsigned short* idsA = (unsigned short*)(smem + OFF_IDS);
    unsigned long long* skA = (unsigned long long*)(smem + OFF_SKEY);

    for (int rr = 0; rr < 4; ++rr) {
        const int row  = w * 4 + rr;
        const int grow = rowBase + row;
        const float* qrow = Qs + row * 68;
        unsigned* pk = pkA + row * CAP;
        unsigned short* ids = idsA + row * TRIM2;
        unsigned long long* skey = skA + row * TRIM2;

        int n = cnt[row];

        if (n < MINC || n > CAP) {
            // rare fallback: bisection threshold over recomputed fp32 scores
            float nx = qrow[lane], ny = qrow[lane + 32];
            float nrm = nx * nx + ny * ny;
            #pragma unroll
            for (int o = 16; o >= 1; o >>= 1) nrm += __shfl_xor_sync(full, nrm, o);
            unsigned lo = 0u, hi = 0xFFFFFFFFu;
            unsigned mid = f2sortable(Z_TAU * sqrtf(nrm) * 0.125f), tu = 0u;
            bool have = false;
            for (int it = 0; it < 34; ++it) {
                int c = 0;
                for (int j = 0; j < 64; ++j) {
                    const float4* k4 = (const float4*)(kb + (size_t)(j * 32 + lane) * D_);
                    float s = 0.0f;
                    #pragma unroll
                    for (int dg = 0; dg < 16; ++dg) {
                        float4 kv = k4[dg];
                        s = fmaf(qrow[dg * 4],     kv.x, s);
                        s = fmaf(qrow[dg * 4 + 1], kv.y, s);
                        s = fmaf(qrow[dg * 4 + 2], kv.z, s);
                        s = fmaf(qrow[dg * 4 + 3], kv.w, s);
                    }
                    c += (f2sortable(s * 0.125f) >= mid);
                }
                #pragma unroll
                for (int o = 16; o >= 1; o >>= 1) c += __shfl_xor_sync(full, c, o);
                if (c >= MINC && c <= CAP) { tu = mid; have = true; break; }
                if (c < MINC) hi = mid; else { lo = mid; tu = mid; have = true; }
                mid = lo + ((hi - lo) >> 1);
                if (mid == lo) { if (!have) tu = lo; break; }
            }
            int base = 0;
            for (int j = 0; j < 64; ++j) {
                int key = j * 32 + lane;
                const float4* k4 = (const float4*)(kb + (size_t)key * D_);
                float s = 0.0f;
                #pragma unroll
                for (int dg = 0; dg < 16; ++dg) {
                    float4 kv = k4[dg];
                    s = fmaf(qrow[dg * 4],     kv.x, s);
                    s = fmaf(qrow[dg * 4 + 1], kv.y, s);
                    s = fmaf(qrow[dg * 4 + 2], kv.z, s);
                    s = fmaf(qrow[dg * 4 + 3], kv.w, s);
                }
                s *= 0.125f;
                bool cnd = f2sortable(s) >= tu;
                unsigned mk = __ballot_sync(full, cnd);
                if (cnd) {
                    int pos = base + __popc(mk & ltmask);
                    if (pos < CAP) pk[pos] = ((unsigned)f2s16(s) << 16) | (unsigned)key;
                }
                base += __popc(mk);
            }
            n = base < CAP ? base : CAP;
        } else {
            const unsigned* candRow = g_cand + (size_t)grow * CAPG;
            for (int i = lane; i < n; i += 32) pk[i] = candRow[i];
        }
        __syncwarp();

        // ---- load my candidates to registers (mc <= 4 since n <= 128) ----
        unsigned mp[4];
        int mc = 0;
        for (int i = lane; i < n; i += 32) mp[mc++] = pk[i];

        // ---- cheap trim: count candidates above packed tau2 ----
        const unsigned tau2p = tau2A[row];
        int cnt2 = 0;
        unsigned msks[4];
        #pragma unroll
        for (int c = 0; c < 4; ++c) {
            msks[c] = __ballot_sync(full, (c < mc) && (mp[c] >= tau2p));
            cnt2 += __popc(msks[c]);
        }

        int m;
        if (cnt2 >= MINC2 && cnt2 <= TRIM2) {
            // O(1) filter compaction
            int base2 = 0;
            #pragma unroll
            for (int c = 0; c < 4; ++c) {
                bool sv = (c < mc) && (mp[c] >= tau2p);
                if (sv) ids[base2 + __popc(msks[c] & ltmask)] = (unsigned short)(mp[c] & 0xFFFFu);
                base2 += __popc(msks[c]);
            }
            m = base2;                      // == cnt2
        } else {
            // fallback: rank-based trim to TRIM
            int rk[4] = {0, 0, 0, 0};
            for (int j = 0; j < n; ++j) {
                unsigned pj = pk[j];
                #pragma unroll
                for (int c = 0; c < 4; ++c) rk[c] += (pj > mp[c]);
            }
            int base2 = 0;
            #pragma unroll
            for (int c = 0; c < 4; ++c) {
                bool sv = (c < mc) && (rk[c] < TRIM);
                unsigned msk = __ballot_sync(full, sv);
                if (sv) ids[base2 + __popc(msk & ltmask)] = (unsigned short)(mp[c] & 0xFFFFu);
                base2 += __popc(msk);
            }
            m = base2;                      // = min(n, TRIM)
        }
        __syncwarp();

        // ---- cooperative fp32 rescore: 4-lane groups, full 32B sectors ----
        const int g4 = lane >> 2, l4 = lane & 3;
        for (int i = 0; i < m; i += 8) {
            int slot = i + g4;
            float s = 0.0f;
            int idx = 0;
            if (slot < m) {
                idx = ids[slot];
                const float4* kr = (const float4*)(kb + (size_t)idx * D_);
                #pragma unroll
                for (int j = 0; j < 4; ++j) {
                    float4 kv = kr[l4 + j * 4];
                    const float* qq = qrow + l4 * 4 + j * 16;
                    s = fmaf(qq[0], kv.x, s); s = fmaf(qq[1], kv.y, s);
                    s = fmaf(qq[2], kv.z, s); s = fmaf(qq[3], kv.w, s);
                }
            }
            s += __shfl_xor_sync(full, s, 1);
            s += __shfl_xor_sync(full, s, 2);
            if (slot < m && l4 == 0) {
                s *= 0.125f;
                skey[slot] = ((unsigned long long)f2sortable(s) << 32)
                           | (unsigned)(2047 - idx);
            }
        }
        __syncwarp();

        // ---- exact top-32 among m (u64: val desc, tie -> lower idx) ----
        float* selv = (float*)pk;            // reuse pk row area
        int*   seli = (int*)(pk + 32);
        unsigned long long fk[2] = {0ull, 0ull};
        int mc2 = 0;
        for (int i = lane; i < m; i += 32) fk[mc2++] = skey[i];
        int rk2[2] = {0, 0};
        for (int j = 0; j < m; ++j) {
            unsigned long long kj = skey[j];
            rk2[0] += (kj > fk[0]);
            rk2[1] += (kj > fk[1]);
        }
        #pragma unroll
        for (int c = 0; c < 2; ++c) {
            if (c < mc2 && rk2[c] < TOPK_) {
                seli[rk2[c]] = 2047 - (int)(fk[c] & 0xFFFFFFFFull);
                selv[rk2[c]] = s2f((unsigned)(fk[c] >> 32));
            }
        }
        __syncwarp();

        // ---- output ----
        float a0 = 0.0f, a1 = 0.0f;
        #pragma unroll
        for (int j = 0; j < TOPK_; ++j) {
            float vv = selv[j];
            const float* vrow = vb + (size_t)seli[j] * D_;
            a0 = fmaf(vv, vrow[lane], a0);
            a1 = fmaf(vv, vrow[lane + 32], a1);
        }
        out[(size_t)grow * D_ + lane]      = a0;
        out[(size_t)grow * D_ + lane + 32] = a1;
        __syncwarp();
    }
}

// ---------------------------------------------------------------------------
extern "C" void kernel_launch(void* const* d_in, const int* in_sizes, int n_in,
                              void* d_out, int out_size)
{
    const float* q = (const float*)d_in[0];
    const float* k = (const float*)d_in[1];
    const float* v = (const float*)d_in[2];
    float* out = (float*)d_out;

    convert_k<<<(B_ * L_ * 8) / 256, 256>>>(k);

    cudaFuncSetAttribute(fused_attn,
                         cudaFuncAttributeMaxDynamicSharedMemorySize, SMEM_A);
    fused_attn<<<NBLK, 256, SMEM_A>>>(q, k, v, out);
}